// round 5
// baseline (speedup 1.0000x reference)
#include <cuda_runtime.h>
#include <cstdint>

#define BB 32
#define TT 2000
#define HH 512
#define LL 256
#define THRESH 0.95f

// Scratch (allocation-free rule: __device__ globals)
__device__ float g_w0[TT * BB];        // [t][b] per-frame "cur" weight
__device__ float g_rem[BB * LL];       // [b][k] remainder weight at k-th fire
__device__ int   g_fire_pos[BB * LL];  // [b][k] frame index of k-th fire
__device__ int   g_nfires[BB];

// ---------------------------------------------------------------------------
// Kernel A: per-batch alpha sum (fp64, correctly rounded) + exact sequential
// CIF scan. 1 block, 1024 threads: warp w reduces batch w; then warp 0 runs
// all 32 batch scans SIMD (lane = batch).
// ---------------------------------------------------------------------------
__global__ void __launch_bounds__(1024, 1)
cif_scan_kernel(const float* __restrict__ alphas, const int* __restrict__ tlen) {
    const int w    = threadIdx.x >> 5;
    const int lane = threadIdx.x & 31;
    __shared__ float s_scale[BB];

    // Phase 1: warp w sums alphas of batch w in double (correctly rounded)
    double s = 0.0;
    const float* ap = alphas + w * TT;
    for (int t = lane; t < TT; t += 32) s += (double)ap[t];
    #pragma unroll
    for (int off = 16; off; off >>= 1) s += __shfl_down_sync(0xffffffffu, s, off);
    if (lane == 0) {
        float sumf = (float)s;                 // fp32 sum (closest to XLA's)
        s_scale[w] = (float)tlen[w] / sumf;    // matches ref: num / sum (fp32 div)
    }
    __syncthreads();

    // Phase 2: warp 0, lane = batch, exact sequential recurrence
    if (threadIdx.x < 32) {
        const int b = threadIdx.x;
        const float scale = s_scale[b];
        const float* a_row = alphas + b * TT;
        float I = 0.0f;
        int   n = 0;
        for (int t = 0; t < TT; ++t) {
            float a = a_row[t] * scale;        // ref: alphas * scale (fp32 mul)
            float d = 1.0f - I;                // dist_completion (old integrate)
            I = I + a;
            bool fire = (I >= THRESH);
            float cur = fire ? d : a;
            g_w0[t * BB + b] = cur;            // coalesced across lanes
            if (fire && (n < LL)) {
                g_fire_pos[b * LL + n] = t;
                g_rem[b * LL + n] = a - cur;   // remainds
            }
            n += fire ? 1 : 0;
            I = fire ? (I - 1.0f) : I;
        }
        g_nfires[b] = (n < LL) ? n : LL;
    }
}

// ---------------------------------------------------------------------------
// Kernel B: one CTA per output token (b,k). 128 threads x float4 covers H=512.
// out[b,k] = rem_{k-1} * h[fire_{k-1}]                     (boundary, k>0)
//          + sum_{t in (fire_{k-1}, fire_k]} w0[t] * h[t]
// Accumulation order matches the reference scan (ascending t, fma chain).
// ---------------------------------------------------------------------------
__global__ void __launch_bounds__(128)
cif_gather_kernel(const float* __restrict__ hidden, float* __restrict__ out) {
    const int k = blockIdx.x;          // token
    const int b = blockIdx.y;          // batch
    const int tid = threadIdx.x;

    float4* o = (float4*)(out + ((size_t)b * LL + k) * HH) + tid;

    const int nf = g_nfires[b];
    if (k >= nf) {                     // unfired tokens are zero (out is poisoned)
        *o = make_float4(0.f, 0.f, 0.f, 0.f);
        return;
    }

    const float4* base = (const float4*)(hidden + (size_t)b * TT * HH);
    const int t_end = g_fire_pos[b * LL + k];

    float4 acc;
    int t0;
    if (k == 0) {
        acc = make_float4(0.f, 0.f, 0.f, 0.f);
        t0 = 0;
    } else {
        const int   tp = g_fire_pos[b * LL + k - 1];
        const float wr = g_rem[b * LL + k - 1];
        float4 h = base[(size_t)tp * (HH / 4) + tid];
        acc = make_float4(wr * h.x, wr * h.y, wr * h.z, wr * h.w);
        t0 = tp + 1;
    }

    // Software-pipelined main loop: prefetch next row while fma'ing current.
    int t = t0;
    float4 h = base[(size_t)t * (HH / 4) + tid];
    float  wv = g_w0[t * BB + b];
    while (t < t_end) {
        float4 hn = base[(size_t)(t + 1) * (HH / 4) + tid];
        float  wn = g_w0[(t + 1) * BB + b];
        acc.x = fmaf(wv, h.x, acc.x);
        acc.y = fmaf(wv, h.y, acc.y);
        acc.z = fmaf(wv, h.z, acc.z);
        acc.w = fmaf(wv, h.w, acc.w);
        h = hn; wv = wn; ++t;
    }
    acc.x = fmaf(wv, h.x, acc.x);
    acc.y = fmaf(wv, h.y, acc.y);
    acc.z = fmaf(wv, h.z, acc.z);
    acc.w = fmaf(wv, h.w, acc.w);

    *o = acc;
}

extern "C" void kernel_launch(void* const* d_in, const int* in_sizes, int n_in,
                              void* d_out, int out_size) {
    const float* hidden = (const float*)d_in[0];
    const float* alphas = (const float*)d_in[1];
    const int*   tlen   = (const int*)d_in[2];
    float* out = (float*)d_out;

    cif_scan_kernel<<<1, 1024>>>(alphas, tlen);
    dim3 grid(LL, BB);
    cif_gather_kernel<<<grid, 128>>>(hidden, out);
}

// round 6
// speedup vs baseline: 1.4528x; 1.4528x over previous
#include <cuda_runtime.h>
#include <cstdint>

#define BB 32
#define TT 2000
#define HH 512
#define LL 256
#define THRESH 0.95f

// Scratch (allocation-free rule: __device__ globals)
__device__ float g_w0[TT * BB];        // [t][b] per-frame "cur" weight
__device__ float g_rem[BB * LL];       // [b][k] remainder weight at k-th fire
__device__ int   g_fire_pos[BB * LL];  // [b][k] frame index of k-th fire
__device__ int   g_nfires[BB];

// ---------------------------------------------------------------------------
// Kernel A: per-batch alpha sum (fp64, correctly rounded) + exact sequential
// CIF scan. 1 block, 1024 threads: warp w reduces batch w; then warp 0 runs
// all 32 batch scans SIMD (lane = batch).
// Scan loads are float4-vectorized and software-pipelined one 8-step block
// ahead so LDG latency overlaps the serial recurrence chain.
// ---------------------------------------------------------------------------
__global__ void __launch_bounds__(1024, 1)
cif_scan_kernel(const float* __restrict__ alphas, const int* __restrict__ tlen) {
    const int w    = threadIdx.x >> 5;
    const int lane = threadIdx.x & 31;
    __shared__ float s_scale[BB];

    // Phase 1: warp w sums alphas of batch w in double (correctly rounded)
    double s = 0.0;
    const float* ap = alphas + w * TT;
    for (int t = lane; t < TT; t += 32) s += (double)ap[t];
    #pragma unroll
    for (int off = 16; off; off >>= 1) s += __shfl_down_sync(0xffffffffu, s, off);
    if (lane == 0) {
        float sumf = (float)s;                 // fp32 sum (closest to XLA's)
        s_scale[w] = (float)tlen[w] / sumf;    // matches ref: num / sum (fp32 div)
    }
    __syncthreads();

    // Phase 2: warp 0, lane = batch, exact sequential recurrence.
    if (threadIdx.x < 32) {
        const int b = threadIdx.x;
        const float scale = s_scale[b];
        // Row is 8000 B from 16B-aligned base -> float4-safe; TT % 8 == 0.
        const float4* a4 = (const float4*)(alphas + b * TT);

        float I = 0.0f;
        int   n = 0;

        float4 p = a4[0];
        float4 q = a4[1];
        for (int t0 = 0; t0 < TT; t0 += 8) {
            float4 pn, qn;
            if (t0 + 8 < TT) {                 // prefetch next block
                pn = a4[(t0 + 8) >> 2];
                qn = a4[((t0 + 8) >> 2) + 1];
            }
            float ab[8] = {p.x, p.y, p.z, p.w, q.x, q.y, q.z, q.w};
            #pragma unroll
            for (int u = 0; u < 8; ++u) {
                const int t = t0 + u;
                float a = ab[u] * scale;       // ref: alphas * scale (fp32 mul)
                float d = 1.0f - I;            // dist_completion (old integrate)
                I = I + a;
                bool fire = (I >= THRESH);
                float cur = fire ? d : a;
                g_w0[t * BB + b] = cur;        // coalesced across lanes
                if (fire && (n < LL)) {
                    g_fire_pos[b * LL + n] = t;
                    g_rem[b * LL + n] = a - cur;   // remainds
                }
                n += fire ? 1 : 0;
                I = fire ? (I - 1.0f) : I;
            }
            p = pn; q = qn;
        }
        g_nfires[b] = (n < LL) ? n : LL;
    }
}

// ---------------------------------------------------------------------------
// Kernel B: one CTA per output token (b,k). 128 threads x float4 covers H=512.
// out[b,k] = rem_{k-1} * h[fire_{k-1}]                     (boundary, k>0)
//          + sum_{t in (fire_{k-1}, fire_k]} w0[t] * h[t]
// Accumulation order matches the reference scan (ascending t, fma chain).
// Depth-2 software pipeline on the hidden-row loads.
// ---------------------------------------------------------------------------
__global__ void __launch_bounds__(128)
cif_gather_kernel(const float* __restrict__ hidden, float* __restrict__ out) {
    const int k = blockIdx.x;          // token
    const int b = blockIdx.y;          // batch
    const int tid = threadIdx.x;

    float4* o = (float4*)(out + ((size_t)b * LL + k) * HH) + tid;

    const int nf = g_nfires[b];
    if (k >= nf) {                     // unfired tokens are zero (out is poisoned)
        *o = make_float4(0.f, 0.f, 0.f, 0.f);
        return;
    }

    const float4* base = (const float4*)(hidden + (size_t)b * TT * HH);
    const int t_end = g_fire_pos[b * LL + k];

    float4 acc;
    int t0;
    if (k == 0) {
        acc = make_float4(0.f, 0.f, 0.f, 0.f);
        t0 = 0;
    } else {
        const int   tp = g_fire_pos[b * LL + k - 1];
        const float wr = g_rem[b * LL + k - 1];
        float4 h = base[(size_t)tp * (HH / 4) + tid];
        acc = make_float4(wr * h.x, wr * h.y, wr * h.z, wr * h.w);
        t0 = tp + 1;
    }

    // Depth-2 pipelined weighted accumulation over t in [t0, t_end].
    int t = t0;
    float4 h0 = base[(size_t)t * (HH / 4) + tid];
    float  w0 = g_w0[t * BB + b];
    float4 h1; float w1;
    if (t + 1 <= t_end) {
        h1 = base[(size_t)(t + 1) * (HH / 4) + tid];
        w1 = g_w0[(t + 1) * BB + b];
    }
    while (t + 1 <= t_end) {
        float4 hn; float wn;
        if (t + 2 <= t_end) {
            hn = base[(size_t)(t + 2) * (HH / 4) + tid];
            wn = g_w0[(t + 2) * BB + b];
        }
        acc.x = fmaf(w0, h0.x, acc.x);
        acc.y = fmaf(w0, h0.y, acc.y);
        acc.z = fmaf(w0, h0.z, acc.z);
        acc.w = fmaf(w0, h0.w, acc.w);
        h0 = h1; w0 = w1;
        h1 = hn; w1 = wn;
        ++t;
    }
    acc.x = fmaf(w0, h0.x, acc.x);
    acc.y = fmaf(w0, h0.y, acc.y);
    acc.z = fmaf(w0, h0.z, acc.z);
    acc.w = fmaf(w0, h0.w, acc.w);

    *o = acc;
}

extern "C" void kernel_launch(void* const* d_in, const int* in_sizes, int n_in,
                              void* d_out, int out_size) {
    const float* hidden = (const float*)d_in[0];
    const float* alphas = (const float*)d_in[1];
    const int*   tlen   = (const int*)d_in[2];
    float* out = (float*)d_out;

    cif_scan_kernel<<<1, 1024>>>(alphas, tlen);
    dim3 grid(LL, BB);
    cif_gather_kernel<<<grid, 128>>>(hidden, out);
}